// round 10
// baseline (speedup 1.0000x reference)
#include <cuda_runtime.h>
#include <cuda_bf16.h>
#include <cstdint>

#define DIMK 2048
#define NEXP 64
#define BM   128             // tokens per CTA
#define NT   128             // 4 warps: 2 k-groups x 2 warps (warp tile m64 x n64)
#define KCH  16              // k per chunk
#define NCHG 64              // chunks per group (1024/16)
#define ROWB 48              // padded row bytes (12r mod 32 distinct -> conflict-free ldm)
#define DELTA 1e-4f
#define RCAP 8192

// per-stage layout (bytes within a group region)
#define A_HI 0
#define A_LO 6144
#define B_HI 12288
#define B_LO 15360
#define STAGEB 18432
#define GROUPB (2 * STAGEB)   // 36864 (2 stages)
#define SMEMB  (2 * GROUPB)   // 73728 total dynamic smem
#define RED_STRIDE 68         // reduction row stride in floats (128*68*4 = 34816 < GROUPB)

__device__ int g_cnt;
__device__ int g_list[RCAP];

// ---------- helpers ----------
__device__ __forceinline__ uint32_t smem_u32(const void* p) {
    uint32_t a;
    asm("{ .reg .u64 t; cvta.to.shared.u64 t, %1; cvt.u32.u64 %0, t; }" : "=r"(a) : "l"(p));
    return a;
}
__device__ __forceinline__ void gbar(int id) {
    asm volatile("bar.sync %0, %1;" :: "r"(id), "r"(64) : "memory");
}
__device__ __forceinline__ void sts128(uint32_t a, uint32_t x, uint32_t y, uint32_t z, uint32_t w) {
    asm volatile("st.shared.v4.b32 [%0], {%1,%2,%3,%4};" :: "r"(a), "r"(x), "r"(y), "r"(z), "r"(w) : "memory");
}
__device__ __forceinline__ void ldm4(uint32_t addr, uint32_t* r) {
    asm volatile("ldmatrix.sync.aligned.m8n8.x4.shared.b16 {%0,%1,%2,%3}, [%4];"
                 : "=r"(r[0]), "=r"(r[1]), "=r"(r[2]), "=r"(r[3]) : "r"(addr));
}
__device__ __forceinline__ void mma16(float* c, const uint32_t* a, uint32_t b0, uint32_t b1) {
    asm volatile(
        "mma.sync.aligned.m16n8k16.row.col.f32.bf16.bf16.f32 "
        "{%0,%1,%2,%3}, {%4,%5,%6,%7}, {%8,%9}, {%0,%1,%2,%3};"
        : "+f"(c[0]), "+f"(c[1]), "+f"(c[2]), "+f"(c[3])
        : "r"(a[0]), "r"(a[1]), "r"(a[2]), "r"(a[3]), "r"(b0), "r"(b1));
}
// fp32x4 -> (hi bf16, lo bf16), packed 2 uints each
__device__ __forceinline__ void split4(float4 v, uint32_t* hu, uint32_t* lu) {
    __nv_bfloat16 hx = __float2bfloat16_rn(v.x);
    __nv_bfloat16 hy = __float2bfloat16_rn(v.y);
    __nv_bfloat16 hz = __float2bfloat16_rn(v.z);
    __nv_bfloat16 hw = __float2bfloat16_rn(v.w);
    __nv_bfloat16 lx = __float2bfloat16_rn(v.x - __bfloat162float(hx));
    __nv_bfloat16 ly = __float2bfloat16_rn(v.y - __bfloat162float(hy));
    __nv_bfloat16 lz = __float2bfloat16_rn(v.z - __bfloat162float(hz));
    __nv_bfloat16 lw = __float2bfloat16_rn(v.w - __bfloat162float(hw));
    hu[0] = (uint32_t)__bfloat16_as_ushort(hx) | ((uint32_t)__bfloat16_as_ushort(hy) << 16);
    hu[1] = (uint32_t)__bfloat16_as_ushort(hz) | ((uint32_t)__bfloat16_as_ushort(hw) << 16);
    lu[0] = (uint32_t)__bfloat16_as_ushort(lx) | ((uint32_t)__bfloat16_as_ushort(ly) << 16);
    lu[1] = (uint32_t)__bfloat16_as_ushort(lz) | ((uint32_t)__bfloat16_as_ushort(lw) << 16);
}

struct Top3 { float v0, v1, v2; int i0, i1; };
__device__ __forceinline__ void t3_insert(Top3& t, float v, int i) {
    if (v > t.v0 || (v == t.v0 && i < t.i0)) {
        t.v2 = t.v1; t.v1 = t.v0; t.i1 = t.i0; t.v0 = v; t.i0 = i;
    } else if (v > t.v1 || (v == t.v1 && i < t.i1)) {
        t.v2 = t.v1; t.v1 = v; t.i1 = i;
    } else if (v > t.v2) {
        t.v2 = v;
    }
}
__device__ __forceinline__ void t3_merge_xor(Top3& t, int m) {
    float pv0 = __shfl_xor_sync(0xFFFFFFFFu, t.v0, m);
    float pv1 = __shfl_xor_sync(0xFFFFFFFFu, t.v1, m);
    float pv2 = __shfl_xor_sync(0xFFFFFFFFu, t.v2, m);
    int   pi0 = __shfl_xor_sync(0xFFFFFFFFu, t.i0, m);
    int   pi1 = __shfl_xor_sync(0xFFFFFFFFu, t.i1, m);
    t3_insert(t, pv0, pi0);
    t3_insert(t, pv1, pi1);
    t3_insert(t, pv2, 0x40000000);
}

// =========================================================================
// Main: 3-pass hi/lo bf16 GEMM, 2 k-groups x 2 warps, warp tile m64n64
// =========================================================================
__global__ __launch_bounds__(NT, 2)
void router_mma(const float* __restrict__ x,
                const float* __restrict__ w,
                float* __restrict__ out_mask,
                float* __restrict__ out_w,
                float* __restrict__ out_i)
{
    extern __shared__ char smem[];
    const uint32_t smb = smem_u32(smem);

    const int tid   = threadIdx.x;
    const int lane  = tid & 31;
    const int wid   = tid >> 5;        // 0..3
    const int grp   = wid >> 1;        // k-group 0/1
    const int wm    = wid & 1;         // m-half within group (tokens wm*64..+64)
    const int tl    = tid & 63;        // fill id within group
    const int gr    = lane >> 2;
    const int gc    = lane & 3;
    const int mbase = blockIdx.x * BM;
    const int barid = grp + 1;

    const uint32_t gb = smb + (uint32_t)grp * GROUPB;

    // ---- fill assignment: per 64-thread group, each thread owns
    //      A rows {tl, 64+tl} and B row tl (16 k-floats each per chunk) ----
    const float4* xr0 = (const float4*)(x + (size_t)(mbase + tl) * DIMK) + grp * 256;
    const float4* xr1 = (const float4*)(x + (size_t)(mbase + 64 + tl) * DIMK) + grp * 256;
    const float4* wr  = (const float4*)(w + (size_t)tl * DIMK) + grp * 256;
    const uint32_t aH0 = gb + A_HI + (uint32_t)tl * ROWB;
    const uint32_t aL0 = gb + A_LO + (uint32_t)tl * ROWB;
    const uint32_t aH1 = gb + A_HI + (uint32_t)(64 + tl) * ROWB;
    const uint32_t aL1 = gb + A_LO + (uint32_t)(64 + tl) * ROWB;
    const uint32_t bH  = gb + B_HI + (uint32_t)tl * ROWB;
    const uint32_t bL  = gb + B_LO + (uint32_t)tl * ROWB;

    // ---- ldmatrix lane offsets (proven mapping; warp covers m64) ----
    const uint32_t a_off = (uint32_t)((wm * 64 + ((lane >> 3) & 1) * 8 + (lane & 7)) * ROWB
                                      + (lane >> 4) * 16);
    const uint32_t b_off = (uint32_t)(((((lane >> 4) & 1) * 8) + (lane & 7)) * ROWB
                                      + ((lane >> 3) & 1) * 16);

    float acc[4][8][4];
#pragma unroll
    for (int i = 0; i < 4; i++)
#pragma unroll
        for (int j = 0; j < 8; j++)
#pragma unroll
            for (int r = 0; r < 4; r++) acc[i][j][r] = 0.0f;

    // ---- prefetch chunk 0 into registers (12 float4) ----
    float4 pa0[4], pa1[4], pb[4];
#pragma unroll
    for (int q = 0; q < 4; q++) { pa0[q] = xr0[q]; pa1[q] = xr1[q]; pb[q] = wr[q]; }

#pragma unroll 1
    for (int c = 0; c < NCHG; c++) {
        const uint32_t stg = (uint32_t)((c & 1) * STAGEB);
        if (c >= 2) gbar(barid);

        // ---- publish chunk c from registers ----
        {
            uint32_t h[8], l[8];
            split4(pa0[0], h + 0, l + 0); split4(pa0[1], h + 2, l + 2);
            split4(pa0[2], h + 4, l + 4); split4(pa0[3], h + 6, l + 6);
            sts128(aH0 + stg,      h[0], h[1], h[2], h[3]);
            sts128(aH0 + stg + 16, h[4], h[5], h[6], h[7]);
            sts128(aL0 + stg,      l[0], l[1], l[2], l[3]);
            sts128(aL0 + stg + 16, l[4], l[5], l[6], l[7]);
            split4(pa1[0], h + 0, l + 0); split4(pa1[1], h + 2, l + 2);
            split4(pa1[2], h + 4, l + 4); split4(pa1[3], h + 6, l + 6);
            sts128(aH1 + stg,      h[0], h[1], h[2], h[3]);
            sts128(aH1 + stg + 16, h[4], h[5], h[6], h[7]);
            sts128(aL1 + stg,      l[0], l[1], l[2], l[3]);
            sts128(aL1 + stg + 16, l[4], l[5], l[6], l[7]);
            split4(pb[0], h + 0, l + 0); split4(pb[1], h + 2, l + 2);
            split4(pb[2], h + 4, l + 4); split4(pb[3], h + 6, l + 6);
            sts128(bH + stg,      h[0], h[1], h[2], h[3]);
            sts128(bH + stg + 16, h[4], h[5], h[6], h[7]);
            sts128(bL + stg,      l[0], l[1], l[2], l[3]);
            sts128(bL + stg + 16, l[4], l[5], l[6], l[7]);
        }
        gbar(barid);

        // ---- prefetch chunk c+1 (overlaps compute below) ----
        if (c + 1 < NCHG) {
#pragma unroll
            for (int q = 0; q < 4; q++) {
                pa0[q] = xr0[(c + 1) * 4 + q];
                pa1[q] = xr1[(c + 1) * 4 + q];
                pb[q]  = wr[(c + 1) * 4 + q];
            }
        }

        // ---- compute: one k16 step, 3 passes, m64n64 ----
        const uint32_t abase = gb + stg + A_HI + a_off;
        const uint32_t bbase = gb + stg + B_HI + b_off;
        uint32_t ah[4][4], al[4][4];
#pragma unroll
        for (int i = 0; i < 4; i++) {
            ldm4(abase + (uint32_t)(i * 16 * ROWB), ah[i]);
            ldm4(abase + (uint32_t)(i * 16 * ROWB) + (A_LO - A_HI), al[i]);
        }
#pragma unroll
        for (int jp = 0; jp < 4; jp++) {
            uint32_t th[4], tl4[4];
            ldm4(bbase + (uint32_t)(jp * 16 * ROWB), th);
            ldm4(bbase + (uint32_t)(jp * 16 * ROWB) + (B_LO - B_HI), tl4);
#pragma unroll
            for (int i = 0; i < 4; i++) {
                mma16(acc[i][2 * jp],     ah[i], th[0],  th[1]);    // hh
                mma16(acc[i][2 * jp],     al[i], th[0],  th[1]);    // lh
                mma16(acc[i][2 * jp],     ah[i], tl4[0], tl4[1]);   // hl
                mma16(acc[i][2 * jp + 1], ah[i], th[2],  th[3]);
                mma16(acc[i][2 * jp + 1], al[i], th[2],  th[3]);
                mma16(acc[i][2 * jp + 1], ah[i], tl4[2], tl4[3]);
            }
        }
    }

    // ---- cross-group reduction (group 1 -> smem -> group 0 adds) ----
    __syncthreads();
    float* redf = (float*)(smem + GROUPB);
    if (grp == 1) {
#pragma unroll
        for (int i = 0; i < 4; i++)
#pragma unroll
            for (int rh = 0; rh < 2; rh++) {
                const int ml = wm * 64 + i * 16 + rh * 8 + gr;
#pragma unroll
                for (int j = 0; j < 8; j++) {
                    float2 v = make_float2(acc[i][j][rh * 2], acc[i][j][rh * 2 + 1]);
                    *(float2*)(redf + ml * RED_STRIDE + 8 * j + 2 * gc) = v;
                }
            }
    }
    __syncthreads();
    if (grp == 0) {
#pragma unroll
        for (int i = 0; i < 4; i++)
#pragma unroll
            for (int rh = 0; rh < 2; rh++) {
                const int ml = wm * 64 + i * 16 + rh * 8 + gr;
#pragma unroll
                for (int j = 0; j < 8; j++) {
                    float2 v = *(float2*)(redf + ml * RED_STRIDE + 8 * j + 2 * gc);
                    acc[i][j][rh * 2]     += v.x;
                    acc[i][j][rh * 2 + 1] += v.y;
                }
            }

        // ---- epilogue: top-2 + flags + outputs ----
#pragma unroll
        for (int i = 0; i < 4; i++) {
#pragma unroll
            for (int rh = 0; rh < 2; rh++) {
                const int m = wm * 64 + i * 16 + rh * 8 + gr;
                Top3 t; t.v0 = -1e30f; t.v1 = -1e30f; t.v2 = -1e30f; t.i0 = 0; t.i1 = 0;
#pragma unroll
                for (int j = 0; j < 8; j++) {
#pragma unroll
                    for (int b = 0; b < 2; b++)
                        t3_insert(t, acc[i][j][rh * 2 + b], 8 * j + 2 * gc + b);
                }
                t3_merge_xor(t, 1);
                t3_merge_xor(t, 2);

                const size_t g = (size_t)(mbase + m);
                if (gc == 0) {
                    float e1  = expf(t.v1 - t.v0);
                    float inv = 1.0f / (1.0f + e1);
                    out_w[g * 2 + 0] = inv;
                    out_w[g * 2 + 1] = e1 * inv;
                    out_i[g * 2 + 0] = (float)t.i0;
                    out_i[g * 2 + 1] = (float)t.i1;
                    if ((t.v0 - t.v1 < DELTA) || (t.v1 - t.v2 < DELTA)) {
                        int slot = atomicAdd(&g_cnt, 1);
                        if (slot < RCAP) g_list[slot] = (int)g;
                    }
                }
                float* mrow = out_mask + g * NEXP + gc * 16;
#pragma unroll
                for (int q = 0; q < 4; q++) {
                    int e0 = gc * 16 + q * 4;
                    float4 mv;
                    mv.x = (e0 + 0 == t.i0 || e0 + 0 == t.i1) ? 1.0f : 0.0f;
                    mv.y = (e0 + 1 == t.i0 || e0 + 1 == t.i1) ? 1.0f : 0.0f;
                    mv.z = (e0 + 2 == t.i0 || e0 + 2 == t.i1) ? 1.0f : 0.0f;
                    mv.w = (e0 + 3 == t.i0 || e0 + 3 == t.i1) ? 1.0f : 0.0f;
                    *(float4*)(mrow + q * 4) = mv;
                }
            }
        }
    }
}

// =========================================================================
// Repair: one CTA per flagged token (wide grid so large cnt also spreads).
// =========================================================================
__global__ __launch_bounds__(256)
void repair_kernel(const float* __restrict__ x,
                   const float* __restrict__ w,
                   float* __restrict__ out_mask,
                   float* __restrict__ out_w,
                   float* __restrict__ out_i)
{
    __shared__ __align__(16) float xs[DIMK];
    __shared__ float lg[NEXP];

    const int tid  = threadIdx.x;
    const int e    = tid >> 2;      // expert
    const int part = tid & 3;       // k-part (interleaved float4)
    int cnt = g_cnt;
    if (cnt > RCAP) cnt = RCAP;

    for (int idx = blockIdx.x; idx < cnt; idx += gridDim.x) {
        const int tok = g_list[idx];
        __syncthreads();
        {
            const float4* xr = (const float4*)(x + (size_t)tok * DIMK);
            for (int q = tid; q < DIMK / 4; q += 256)
                ((float4*)xs)[q] = xr[q];
        }
        __syncthreads();

        const float4* wrow = (const float4*)(w + (size_t)e * DIMK);
        const float4* xp   = (const float4*)xs;
        float4 accv = make_float4(0, 0, 0, 0);
#pragma unroll 8
        for (int q = 0; q < 128; q++) {
            float4 xv = xp[4 * q + part];
            float4 wv = wrow[4 * q + part];
            accv.x = fmaf(xv.x, wv.x, accv.x);
            accv.y = fmaf(xv.y, wv.y, accv.y);
            accv.z = fmaf(xv.z, wv.z, accv.z);
            accv.w = fmaf(xv.w, wv.w, accv.w);
        }
        float s = (accv.x + accv.y) + (accv.z + accv.w);
        s += __shfl_xor_sync(0xFFFFFFFFu, s, 1);
        s += __shfl_xor_sync(0xFFFFFFFFu, s, 2);
        if (part == 0) lg[e] = s;
        __syncthreads();

        if (tid < 32) {
            Top3 t; t.v0 = -1e30f; t.v1 = -1e30f; t.v2 = -1e30f; t.i0 = 0; t.i1 = 0;
            t3_insert(t, lg[tid], tid);
            t3_insert(t, lg[tid + 32], tid + 32);
            t3_merge_xor(t, 1);
            t3_merge_xor(t, 2);
            t3_merge_xor(t, 4);
            t3_merge_xor(t, 8);
            t3_merge_xor(t, 16);

            int i0 = __shfl_sync(0xFFFFFFFFu, t.i0, 0);
            int i1 = __shfl_sync(0xFFFFFFFFu, t.i1, 0);
            if (tid == 0) {
                float e1  = expf(t.v1 - t.v0);
                float inv = 1.0f / (1.0f + e1);
                out_w[(size_t)tok * 2 + 0] = inv;
                out_w[(size_t)tok * 2 + 1] = e1 * inv;
                out_i[(size_t)tok * 2 + 0] = (float)i0;
                out_i[(size_t)tok * 2 + 1] = (float)i1;
            }
            out_mask[(size_t)tok * NEXP + tid] =
                (tid == i0 || tid == i1) ? 1.0f : 0.0f;
            out_mask[(size_t)tok * NEXP + tid + 32] =
                (tid + 32 == i0 || tid + 32 == i1) ? 1.0f : 0.0f;
        }
    }
}

extern "C" void kernel_launch(void* const* d_in, const int* in_sizes, int n_in,
                              void* d_out, int out_size) {
    const float* x = (const float*)d_in[0];   // (N, 2048) fp32
    const float* w = (const float*)d_in[1];   // (64, 2048) fp32
    int n_tokens = in_sizes[0] / DIMK;        // 32768

    float* out      = (float*)d_out;
    float* out_mask = out;                                  // N*64
    float* out_w    = out + (size_t)n_tokens * NEXP;        // N*2
    float* out_i    = out_w + (size_t)n_tokens * 2;         // N*2

    static void* cnt_addr = nullptr;
    if (!cnt_addr) {
        cudaGetSymbolAddress(&cnt_addr, g_cnt);
        cudaFuncSetAttribute(router_mma, cudaFuncAttributeMaxDynamicSharedMemorySize, SMEMB);
    }

    cudaMemsetAsync(cnt_addr, 0, sizeof(int));
    router_mma<<<n_tokens / BM, NT, SMEMB>>>(x, w, out_mask, out_w, out_i);
    repair_kernel<<<1024, 256>>>(x, w, out_mask, out_w, out_i);
}

// round 13
// speedup vs baseline: 1.1697x; 1.1697x over previous
#include <cuda_runtime.h>
#include <cuda_bf16.h>
#include <cstdint>

#define DIMK 2048
#define NEXP 64
#define BM   128             // tokens per CTA
#define NT   256             // 8 warps: 2 k-groups x 4 warps (warp tile m32 x n64)
#define KCH  16              // k per chunk
#define NCHG 64              // chunks per group (1024/16)
#define ROWB 48              // padded row bytes (12r mod 32 distinct -> conflict-free ldm)
#define DELTA 1e-4f
#define FCAP 64              // per-CTA flagged-token capacity

// per-stage layout (bytes within a group region)
#define A_HI 0
#define A_LO 6144
#define B_HI 12288
#define B_LO 15360
#define STAGEB 18432
#define GROUPB (2 * STAGEB)   // 36864 (2 stages)
#define SMEMB  (2 * GROUPB)   // 73728 total dynamic smem
#define RED_STRIDE 68         // reduction row stride in floats

// ---------- helpers ----------
__device__ __forceinline__ uint32_t smem_u32(const void* p) {
    uint32_t a;
    asm("{ .reg .u64 t; cvta.to.shared.u64 t, %1; cvt.u32.u64 %0, t; }" : "=r"(a) : "l"(p));
    return a;
}
__device__ __forceinline__ void gbar(int id) {
    asm volatile("bar.sync %0, %1;" :: "r"(id), "r"(128) : "memory");
}
__device__ __forceinline__ void sts128(uint32_t a, uint32_t x, uint32_t y, uint32_t z, uint32_t w) {
    asm volatile("st.shared.v4.b32 [%0], {%1,%2,%3,%4};" :: "r"(a), "r"(x), "r"(y), "r"(z), "r"(w) : "memory");
}
__device__ __forceinline__ void ldm4(uint32_t addr, uint32_t* r) {
    asm volatile("ldmatrix.sync.aligned.m8n8.x4.shared.b16 {%0,%1,%2,%3}, [%4];"
                 : "=r"(r[0]), "=r"(r[1]), "=r"(r[2]), "=r"(r[3]) : "r"(addr));
}
__device__ __forceinline__ void mma16(float* c, const uint32_t* a, uint32_t b0, uint32_t b1) {
    asm volatile(
        "mma.sync.aligned.m16n8k16.row.col.f32.bf16.bf16.f32 "
        "{%0,%1,%2,%3}, {%4,%5,%6,%7}, {%8,%9}, {%0,%1,%2,%3};"
        : "+f"(c[0]), "+f"(c[1]), "+f"(c[2]), "+f"(c[3])
        : "r"(a[0]), "r"(a[1]), "r"(a[2]), "r"(a[3]), "r"(b0), "r"(b1));
}
// fp32x4 -> (hi bf16, lo bf16), packed 2 uints each
__device__ __forceinline__ void split4(float4 v, uint32_t* hu, uint32_t* lu) {
    __nv_bfloat16 hx = __float2bfloat16_rn(v.x);
    __nv_bfloat16 hy = __float2bfloat16_rn(v.y);
    __nv_bfloat16 hz = __float2bfloat16_rn(v.z);
    __nv_bfloat16 hw = __float2bfloat16_rn(v.w);
    __nv_bfloat16 lx = __float2bfloat16_rn(v.x - __bfloat162float(hx));
    __nv_bfloat16 ly = __float2bfloat16_rn(v.y - __bfloat162float(hy));
    __nv_bfloat16 lz = __float2bfloat16_rn(v.z - __bfloat162float(hz));
    __nv_bfloat16 lw = __float2bfloat16_rn(v.w - __bfloat162float(hw));
    hu[0] = (uint32_t)__bfloat16_as_ushort(hx) | ((uint32_t)__bfloat16_as_ushort(hy) << 16);
    hu[1] = (uint32_t)__bfloat16_as_ushort(hz) | ((uint32_t)__bfloat16_as_ushort(hw) << 16);
    lu[0] = (uint32_t)__bfloat16_as_ushort(lx) | ((uint32_t)__bfloat16_as_ushort(ly) << 16);
    lu[1] = (uint32_t)__bfloat16_as_ushort(lz) | ((uint32_t)__bfloat16_as_ushort(lw) << 16);
}

struct Top3 { float v0, v1, v2; int i0, i1; };
__device__ __forceinline__ void t3_insert(Top3& t, float v, int i) {
    if (v > t.v0 || (v == t.v0 && i < t.i0)) {
        t.v2 = t.v1; t.v1 = t.v0; t.i1 = t.i0; t.v0 = v; t.i0 = i;
    } else if (v > t.v1 || (v == t.v1 && i < t.i1)) {
        t.v2 = t.v1; t.v1 = v; t.i1 = i;
    } else if (v > t.v2) {
        t.v2 = v;
    }
}
__device__ __forceinline__ void t3_merge_xor(Top3& t, int m) {
    float pv0 = __shfl_xor_sync(0xFFFFFFFFu, t.v0, m);
    float pv1 = __shfl_xor_sync(0xFFFFFFFFu, t.v1, m);
    float pv2 = __shfl_xor_sync(0xFFFFFFFFu, t.v2, m);
    int   pi0 = __shfl_xor_sync(0xFFFFFFFFu, t.i0, m);
    int   pi1 = __shfl_xor_sync(0xFFFFFFFFu, t.i1, m);
    t3_insert(t, pv0, pi0);
    t3_insert(t, pv1, pi1);
    t3_insert(t, pv2, 0x40000000);
}

// =========================================================================
// Single kernel: 3-pass hi/lo bf16 GEMM (2 k-groups, warp tile m32n64)
// + top-2 epilogue + IN-CTA exact repair of low-margin tokens.
// =========================================================================
__global__ __launch_bounds__(NT, 2)
void router_mma(const float* __restrict__ x,
                const float* __restrict__ w,
                float* __restrict__ out_mask,
                float* __restrict__ out_w,
                float* __restrict__ out_i)
{
    extern __shared__ char smem[];
    const uint32_t smb = smem_u32(smem);

    __shared__ int s_cnt;
    __shared__ int s_list[FCAP];

    const int tid   = threadIdx.x;
    const int lane  = tid & 31;
    const int wid   = tid >> 5;        // 0..7
    const int grp   = wid >> 2;        // k-group 0/1
    const int wid_l = wid & 3;         // warp within group
    const int tl    = tid & 127;       // fill id within group
    const int gr    = lane >> 2;
    const int gc    = lane & 3;
    const int mbase = blockIdx.x * BM;
    const int barid = grp + 1;

    if (tid == 0) s_cnt = 0;

    const uint32_t gb = smb + (uint32_t)grp * GROUPB;

    // ---- fill assignment ----
    const float4* xr = (const float4*)(x + (size_t)(mbase + tl) * DIMK) + grp * 256;
    const int br = tl >> 1, bh = tl & 1;
    const float4* wr = (const float4*)(w + (size_t)br * DIMK) + grp * 256 + bh * 2;
    const uint32_t aH = gb + A_HI + (uint32_t)tl * ROWB;
    const uint32_t aL = gb + A_LO + (uint32_t)tl * ROWB;
    const uint32_t bH = gb + B_HI + (uint32_t)(br * ROWB + bh * 16);
    const uint32_t bL = gb + B_LO + (uint32_t)(br * ROWB + bh * 16);

    // ---- ldmatrix lane offsets (proven mapping) ----
    const uint32_t a_off = (uint32_t)((wid_l * 32 + ((lane >> 3) & 1) * 8 + (lane & 7)) * ROWB
                                      + (lane >> 4) * 16);
    const uint32_t b_off = (uint32_t)(((((lane >> 4) & 1) * 8) + (lane & 7)) * ROWB
                                      + ((lane >> 3) & 1) * 16);

    float acc[2][8][4];
#pragma unroll
    for (int i = 0; i < 2; i++)
#pragma unroll
        for (int j = 0; j < 8; j++)
#pragma unroll
            for (int r = 0; r < 4; r++) acc[i][j][r] = 0.0f;

    // ---- prefetch chunk 0 into registers ----
    float4 pa[4], pb[2];
#pragma unroll
    for (int q = 0; q < 4; q++) pa[q] = xr[q];
    pb[0] = wr[0];
    pb[1] = wr[1];

#pragma unroll 1
    for (int c = 0; c < NCHG; c++) {
        const uint32_t stg = (uint32_t)((c & 1) * STAGEB);
        if (c >= 2) gbar(barid);

        // ---- publish chunk c from registers ----
        {
            uint32_t h[8], l[8];
            split4(pa[0], h + 0, l + 0); split4(pa[1], h + 2, l + 2);
            split4(pa[2], h + 4, l + 4); split4(pa[3], h + 6, l + 6);
            sts128(aH + stg,      h[0], h[1], h[2], h[3]);
            sts128(aH + stg + 16, h[4], h[5], h[6], h[7]);
            sts128(aL + stg,      l[0], l[1], l[2], l[3]);
            sts128(aL + stg + 16, l[4], l[5], l[6], l[7]);
            uint32_t hb[4], lb[4];
            split4(pb[0], hb + 0, lb + 0); split4(pb[1], hb + 2, lb + 2);
            sts128(bH + stg, hb[0], hb[1], hb[2], hb[3]);
            sts128(bL + stg, lb[0], lb[1], lb[2], lb[3]);
        }
        gbar(barid);

        // ---- prefetch chunk c+1 (overlaps compute below) ----
        if (c + 1 < NCHG) {
#pragma unroll
            for (int q = 0; q < 4; q++) pa[q] = xr[(c + 1) * 4 + q];
            pb[0] = wr[(c + 1) * 4 + 0];
            pb[1] = wr[(c + 1) * 4 + 1];
        }

        // ---- compute: one k16 step, 3 passes ----
        const uint32_t abase = gb + stg + A_HI + a_off;
        const uint32_t bbase = gb + stg + B_HI + b_off;
        uint32_t ah[2][4], al[2][4];
#pragma unroll
        for (int i = 0; i < 2; i++) {
            ldm4(abase + (uint32_t)(i * 16 * ROWB), ah[i]);
            ldm4(abase + (uint32_t)(i * 16 * ROWB) + (A_LO - A_HI), al[i]);
        }
#pragma unroll
        for (int jp = 0; jp < 4; jp++) {
            uint32_t th[4], tl4[4];
            ldm4(bbase + (uint32_t)(jp * 16 * ROWB), th);
            ldm4(bbase + (uint32_t)(jp * 16 * ROWB) + (B_LO - B_HI), tl4);
#pragma unroll
            for (int i = 0; i < 2; i++) {
                mma16(acc[i][2 * jp],     ah[i], th[0],  th[1]);    // hh
                mma16(acc[i][2 * jp],     al[i], th[0],  th[1]);    // lh
                mma16(acc[i][2 * jp],     ah[i], tl4[0], tl4[1]);   // hl
                mma16(acc[i][2 * jp + 1], ah[i], th[2],  th[3]);
                mma16(acc[i][2 * jp + 1], al[i], th[2],  th[3]);
                mma16(acc[i][2 * jp + 1], ah[i], tl4[2], tl4[3]);
            }
        }
    }

    // ---- cross-group reduction (group 1 -> smem -> group 0 adds) ----
    __syncthreads();
    float* redf = (float*)(smem + GROUPB);
    if (grp == 1) {
#pragma unroll
        for (int i = 0; i < 2; i++)
#pragma unroll
            for (int rh = 0; rh < 2; rh++) {
                const int ml = wid_l * 32 + i * 16 + rh * 8 + gr;
#pragma unroll
                for (int j = 0; j < 8; j++) {
                    float2 v = make_float2(acc[i][j][rh * 2], acc[i][j][rh * 2 + 1]);
                    *(float2*)(redf + ml * RED_STRIDE + 8 * j + 2 * gc) = v;
                }
            }
    }
    __syncthreads();
    if (grp == 0) {
#pragma unroll
        for (int i = 0; i < 2; i++)
#pragma unroll
            for (int rh = 0; rh < 2; rh++) {
                const int ml = wid_l * 32 + i * 16 + rh * 8 + gr;
#pragma unroll
                for (int j = 0; j < 8; j++) {
                    float2 v = *(float2*)(redf + ml * RED_STRIDE + 8 * j + 2 * gc);
                    acc[i][j][rh * 2]     += v.x;
                    acc[i][j][rh * 2 + 1] += v.y;
                }
            }

        // ---- epilogue: top-2 + smem flags + outputs ----
#pragma unroll
        for (int i = 0; i < 2; i++) {
#pragma unroll
            for (int rh = 0; rh < 2; rh++) {
                const int m = wid_l * 32 + i * 16 + rh * 8 + gr;
                Top3 t; t.v0 = -1e30f; t.v1 = -1e30f; t.v2 = -1e30f; t.i0 = 0; t.i1 = 0;
#pragma unroll
                for (int j = 0; j < 8; j++) {
#pragma unroll
                    for (int b = 0; b < 2; b++)
                        t3_insert(t, acc[i][j][rh * 2 + b], 8 * j + 2 * gc + b);
                }
                t3_merge_xor(t, 1);
                t3_merge_xor(t, 2);

                const size_t g = (size_t)(mbase + m);
                if (gc == 0) {
                    float e1  = expf(t.v1 - t.v0);
                    float inv = 1.0f / (1.0f + e1);
                    out_w[g * 2 + 0] = inv;
                    out_w[g * 2 + 1] = e1 * inv;
                    out_i[g * 2 + 0] = (float)t.i0;
                    out_i[g * 2 + 1] = (float)t.i1;
                    if ((t.v0 - t.v1 < DELTA) || (t.v1 - t.v2 < DELTA)) {
                        int slot = atomicAdd(&s_cnt, 1);
                        if (slot < FCAP) s_list[slot] = m;
                    }
                }
                float* mrow = out_mask + g * NEXP + gc * 16;
#pragma unroll
                for (int q = 0; q < 4; q++) {
                    int e0 = gc * 16 + q * 4;
                    float4 mv;
                    mv.x = (e0 + 0 == t.i0 || e0 + 0 == t.i1) ? 1.0f : 0.0f;
                    mv.y = (e0 + 1 == t.i0 || e0 + 1 == t.i1) ? 1.0f : 0.0f;
                    mv.z = (e0 + 2 == t.i0 || e0 + 2 == t.i1) ? 1.0f : 0.0f;
                    mv.w = (e0 + 3 == t.i0 || e0 + 3 == t.i1) ? 1.0f : 0.0f;
                    *(float4*)(mrow + q * 4) = mv;
                }
            }
        }
    }

    // ================= in-CTA exact repair of flagged tokens =================
    __syncthreads();
    int cnt = s_cnt;
    if (cnt > FCAP) cnt = FCAP;
    if (cnt > 0) {
        float* xs = (float*)smem;            // 8KB, stage area is dead now
        float* lg = (float*)(smem + 8192);   // 64 floats
        const int e    = tid >> 2;           // expert
        const int part = tid & 3;            // interleaved float4 k-part

        for (int it = 0; it < cnt; it++) {
            const int m = s_list[it];
            const size_t tok = (size_t)(mbase + m);
            __syncthreads();
            {
                const float4* xrow = (const float4*)(x + tok * DIMK);
                for (int q = tid; q < DIMK / 4; q += NT)
                    ((float4*)xs)[q] = xrow[q];
            }
            __syncthreads();

            const float4* wrow = (const float4*)(w + (size_t)e * DIMK);
            const float4* xp   = (const float4*)xs;
            float4 accv = make_float4(0, 0, 0, 0);
#pragma unroll 8
            for (int q = 0; q < 128; q++) {
                float4 xv = xp[4 * q + part];
                float4 wv = wrow[4 * q + part];
                accv.x = fmaf(xv.x, wv.x, accv.x);
                accv.y = fmaf(xv.y, wv.y, accv.y);
                accv.z = fmaf(xv.z, wv.z, accv.z);
                accv.w = fmaf(xv.w, wv.w, accv.w);
            }
            float s = (accv.x + accv.y) + (accv.z + accv.w);
            s += __shfl_xor_sync(0xFFFFFFFFu, s, 1);
            s += __shfl_xor_sync(0xFFFFFFFFu, s, 2);
            if (part == 0) lg[e] = s;
            __syncthreads();

            if (tid < 32) {
                Top3 t; t.v0 = -1e30f; t.v1 = -1e30f; t.v2 = -1e30f; t.i0 = 0; t.i1 = 0;
                t3_insert(t, lg[tid], tid);
                t3_insert(t, lg[tid + 32], tid + 32);
                t3_merge_xor(t, 1);
                t3_merge_xor(t, 2);
                t3_merge_xor(t, 4);
                t3_merge_xor(t, 8);
                t3_merge_xor(t, 16);

                int i0 = __shfl_sync(0xFFFFFFFFu, t.i0, 0);
                int i1 = __shfl_sync(0xFFFFFFFFu, t.i1, 0);
                if (tid == 0) {
                    float e1  = expf(t.v1 - t.v0);
                    float inv = 1.0f / (1.0f + e1);
                    out_w[tok * 2 + 0] = inv;
                    out_w[tok * 2 + 1] = e1 * inv;
                    out_i[tok * 2 + 0] = (float)i0;
                    out_i[tok * 2 + 1] = (float)i1;
                }
                out_mask[tok * NEXP + tid] =
                    (tid == i0 || tid == i1) ? 1.0f : 0.0f;
                out_mask[tok * NEXP + tid + 32] =
                    (tid + 32 == i0 || tid + 32 == i1) ? 1.0f : 0.0f;
            }
        }
    }
}

extern "C" void kernel_launch(void* const* d_in, const int* in_sizes, int n_in,
                              void* d_out, int out_size) {
    const float* x = (const float*)d_in[0];   // (N, 2048) fp32
    const float* w = (const float*)d_in[1];   // (64, 2048) fp32
    int n_tokens = in_sizes[0] / DIMK;        // 32768

    float* out      = (float*)d_out;
    float* out_mask = out;                                  // N*64
    float* out_w    = out + (size_t)n_tokens * NEXP;        // N*2
    float* out_i    = out_w + (size_t)n_tokens * 2;         // N*2

    static bool attr_done = false;
    if (!attr_done) {
        cudaFuncSetAttribute(router_mma, cudaFuncAttributeMaxDynamicSharedMemorySize, SMEMB);
        attr_done = true;
    }

    router_mma<<<n_tokens / BM, NT, SMEMB>>>(x, w, out_mask, out_w, out_i);
}

// round 14
// speedup vs baseline: 1.4678x; 1.2549x over previous
#include <cuda_runtime.h>
#include <cuda_bf16.h>
#include <cstdint>

#define DIMK 2048
#define NEXP 64
#define BM   128             // tokens per CTA
#define NT   256             // 8 warps: 2 k-groups x 4 warps (warp tile m32 x n64)
#define KCH  16              // k per chunk
#define NCHG 64              // chunks per group (1024/16)
#define ROWB 48              // padded row bytes (12r mod 32 distinct -> conflict-free ldm)
#define DELTA 1e-4f
#define FCAP 64              // per-CTA flagged-token capacity
#define RSTRIDE4 (32 * (DIMK / 4))   // float4 stride between 32-row groups (16384)

// per-stage layout (bytes within a group region)
#define A_HI 0
#define A_LO 6144
#define B_HI 12288
#define B_LO 15360
#define STAGEB 18432
#define GROUPB (2 * STAGEB)   // 36864 (2 stages)
#define SMEMB  (2 * GROUPB)   // 73728 total dynamic smem
#define RED_STRIDE 68         // reduction row stride in floats

// ---------- helpers ----------
__device__ __forceinline__ uint32_t smem_u32(const void* p) {
    uint32_t a;
    asm("{ .reg .u64 t; cvta.to.shared.u64 t, %1; cvt.u32.u64 %0, t; }" : "=r"(a) : "l"(p));
    return a;
}
__device__ __forceinline__ void gbar(int id) {
    asm volatile("bar.sync %0, %1;" :: "r"(id), "r"(128) : "memory");
}
__device__ __forceinline__ void sts64(uint32_t a, uint32_t x, uint32_t y) {
    asm volatile("st.shared.v2.b32 [%0], {%1,%2};" :: "r"(a), "r"(x), "r"(y) : "memory");
}
__device__ __forceinline__ void ldm4(uint32_t addr, uint32_t* r) {
    asm volatile("ldmatrix.sync.aligned.m8n8.x4.shared.b16 {%0,%1,%2,%3}, [%4];"
                 : "=r"(r[0]), "=r"(r[1]), "=r"(r[2]), "=r"(r[3]) : "r"(addr));
}
__device__ __forceinline__ void mma16(float* c, const uint32_t* a, uint32_t b0, uint32_t b1) {
    asm volatile(
        "mma.sync.aligned.m16n8k16.row.col.f32.bf16.bf16.f32 "
        "{%0,%1,%2,%3}, {%4,%5,%6,%7}, {%8,%9}, {%0,%1,%2,%3};"
        : "+f"(c[0]), "+f"(c[1]), "+f"(c[2]), "+f"(c[3])
        : "r"(a[0]), "r"(a[1]), "r"(a[2]), "r"(a[3]), "r"(b0), "r"(b1));
}
// fp32x4 -> (hi bf16, lo bf16), packed 2 uints each
__device__ __forceinline__ void split4(float4 v, uint32_t* hu, uint32_t* lu) {
    __nv_bfloat16 hx = __float2bfloat16_rn(v.x);
    __nv_bfloat16 hy = __float2bfloat16_rn(v.y);
    __nv_bfloat16 hz = __float2bfloat16_rn(v.z);
    __nv_bfloat16 hw = __float2bfloat16_rn(v.w);
    __nv_bfloat16 lx = __float2bfloat16_rn(v.x - __bfloat162float(hx));
    __nv_bfloat16 ly = __float2bfloat16_rn(v.y - __bfloat162float(hy));
    __nv_bfloat16 lz = __float2bfloat16_rn(v.z - __bfloat162float(hz));
    __nv_bfloat16 lw = __float2bfloat16_rn(v.w - __bfloat162float(hw));
    hu[0] = (uint32_t)__bfloat16_as_ushort(hx) | ((uint32_t)__bfloat16_as_ushort(hy) << 16);
    hu[1] = (uint32_t)__bfloat16_as_ushort(hz) | ((uint32_t)__bfloat16_as_ushort(hw) << 16);
    lu[0] = (uint32_t)__bfloat16_as_ushort(lx) | ((uint32_t)__bfloat16_as_ushort(ly) << 16);
    lu[1] = (uint32_t)__bfloat16_as_ushort(lz) | ((uint32_t)__bfloat16_as_ushort(lw) << 16);
}

struct Top3 { float v0, v1, v2; int i0, i1; };
__device__ __forceinline__ void t3_insert(Top3& t, float v, int i) {
    if (v > t.v0 || (v == t.v0 && i < t.i0)) {
        t.v2 = t.v1; t.v1 = t.v0; t.i1 = t.i0; t.v0 = v; t.i0 = i;
    } else if (v > t.v1 || (v == t.v1 && i < t.i1)) {
        t.v2 = t.v1; t.v1 = v; t.i1 = i;
    } else if (v > t.v2) {
        t.v2 = v;
    }
}
__device__ __forceinline__ void t3_merge_xor(Top3& t, int m) {
    float pv0 = __shfl_xor_sync(0xFFFFFFFFu, t.v0, m);
    float pv1 = __shfl_xor_sync(0xFFFFFFFFu, t.v1, m);
    float pv2 = __shfl_xor_sync(0xFFFFFFFFu, t.v2, m);
    int   pi0 = __shfl_xor_sync(0xFFFFFFFFu, t.i0, m);
    int   pi1 = __shfl_xor_sync(0xFFFFFFFFu, t.i1, m);
    t3_insert(t, pv0, pi0);
    t3_insert(t, pv1, pi1);
    t3_insert(t, pv2, 0x40000000);
}

// =========================================================================
// Single kernel: 3-pass hi/lo bf16 GEMM (2 k-groups, warp tile m32n64)
// + coalesced fill (4 lanes per gmem row) + top-2 epilogue
// + IN-CTA exact repair of low-margin tokens.
// =========================================================================
__global__ __launch_bounds__(NT, 2)
void router_mma(const float* __restrict__ x,
                const float* __restrict__ w,
                float* __restrict__ out_mask,
                float* __restrict__ out_w,
                float* __restrict__ out_i)
{
    extern __shared__ char smem[];
    const uint32_t smb = smem_u32(smem);

    __shared__ int s_cnt;
    __shared__ int s_list[FCAP];

    const int tid   = threadIdx.x;
    const int lane  = tid & 31;
    const int wid   = tid >> 5;        // 0..7
    const int grp   = wid >> 2;        // k-group 0/1
    const int wid_l = wid & 3;         // warp within group
    const int tl    = tid & 127;       // fill id within group
    const int gr    = lane >> 2;
    const int gc    = lane & 3;
    const int mbase = blockIdx.x * BM;
    const int barid = grp + 1;

    if (tid == 0) s_cnt = 0;

    const uint32_t gb = smb + (uint32_t)grp * GROUPB;

    // ---- coalesced fill assignment: 4 lanes per row, 8 rows/warp/instr ----
    const int frow = tl >> 2;          // base row 0..31 (A rows +32q, B rows +32q)
    const int fcol = tl & 3;           // float4 slot within the 64B chunk segment
    const float4* xr = (const float4*)(x + (size_t)(mbase + frow) * DIMK) + grp * 256 + fcol;
    const float4* wr = (const float4*)(w + (size_t)frow * DIMK) + grp * 256 + fcol;
    const uint32_t aQ0 = gb + A_HI + (uint32_t)(frow * ROWB + fcol * 8);
    const uint32_t bQ0 = gb + B_HI + (uint32_t)(frow * ROWB + fcol * 8);

    // ---- ldmatrix lane offsets (proven mapping) ----
    const uint32_t a_off = (uint32_t)((wid_l * 32 + ((lane >> 3) & 1) * 8 + (lane & 7)) * ROWB
                                      + (lane >> 4) * 16);
    const uint32_t b_off = (uint32_t)(((((lane >> 4) & 1) * 8) + (lane & 7)) * ROWB
                                      + ((lane >> 3) & 1) * 16);

    float acc[2][8][4];
#pragma unroll
    for (int i = 0; i < 2; i++)
#pragma unroll
        for (int j = 0; j < 8; j++)
#pragma unroll
            for (int r = 0; r < 4; r++) acc[i][j][r] = 0.0f;

    // ---- prefetch chunk 0 into registers ----
    float4 pa[4], pb[2];
#pragma unroll
    for (int q = 0; q < 4; q++) pa[q] = xr[q * RSTRIDE4];
    pb[0] = wr[0];
    pb[1] = wr[RSTRIDE4];

#pragma unroll 1
    for (int c = 0; c < NCHG; c++) {
        const uint32_t stg = (uint32_t)((c & 1) * STAGEB);
        if (c >= 2) gbar(barid);

        // ---- publish chunk c from registers (A rows frow+32q, B rows frow+32q) ----
        {
            uint32_t h[2], l[2];
#pragma unroll
            for (int q = 0; q < 4; q++) {
                split4(pa[q], h, l);
                sts64(aQ0 + (uint32_t)(q * 32 * ROWB) + stg, h[0], h[1]);
                sts64(aQ0 + (uint32_t)(q * 32 * ROWB) + stg + (A_LO - A_HI), l[0], l[1]);
            }
#pragma unroll
            for (int q = 0; q < 2; q++) {
                split4(pb[q], h, l);
                sts64(bQ0 + (uint32_t)(q * 32 * ROWB) + stg, h[0], h[1]);
                sts64(bQ0 + (uint32_t)(q * 32 * ROWB) + stg + (B_LO - B_HI), l[0], l[1]);
            }
        }
        gbar(barid);

        // ---- prefetch chunk c+1 (overlaps compute below) ----
        if (c + 1 < NCHG) {
#pragma unroll
            for (int q = 0; q < 4; q++) pa[q] = xr[(c + 1) * 4 + q * RSTRIDE4];
            pb[0] = wr[(c + 1) * 4];
            pb[1] = wr[(c + 1) * 4 + RSTRIDE4];
        }

        // ---- compute: one k16 step, 3 passes ----
        const uint32_t abase = gb + stg + A_HI + a_off;
        const uint32_t bbase = gb + stg + B_HI + b_off;
        uint32_t ah[2][4], al[2][4];
#pragma unroll
        for (int i = 0; i < 2; i++) {
            ldm4(abase + (uint32_t)(i * 16 * ROWB), ah[i]);
            ldm4(abase + (uint32_t)(i * 16 * ROWB) + (A_LO - A_HI), al[i]);
        }
#pragma unroll
        for (int jp = 0; jp < 4; jp++) {
            uint32_t th[4], tl4[4];
            ldm4(bbase + (uint32_t)(jp * 16 * ROWB), th);
            ldm4(bbase + (uint32_t)(jp * 16 * ROWB) + (B_LO - B_HI), tl4);
#pragma unroll
            for (int i = 0; i < 2; i++) {
                mma16(acc[i][2 * jp],     ah[i], th[0],  th[1]);    // hh
                mma16(acc[i][2 * jp],     al[i], th[0],  th[1]);    // lh
                mma16(acc[i][2 * jp],     ah[i], tl4[0], tl4[1]);   // hl
                mma16(acc[i][2 * jp + 1], ah[i], th[2],  th[3]);
                mma16(acc[i][2 * jp + 1], al[i], th[2],  th[3]);
                mma16(acc[i][2 * jp + 1], ah[i], tl4[2], tl4[3]);
            }
        }
    }

    // ---- cross-group reduction (group 1 -> smem -> group 0 adds) ----
    __syncthreads();
    float* redf = (float*)(smem + GROUPB);
    if (grp == 1) {
#pragma unroll
        for (int i = 0; i < 2; i++)
#pragma unroll
            for (int rh = 0; rh < 2; rh++) {
                const int ml = wid_l * 32 + i * 16 + rh * 8 + gr;
#pragma unroll
                for (int j = 0; j < 8; j++) {
                    float2 v = make_float2(acc[i][j][rh * 2], acc[i][j][rh * 2 + 1]);
                    *(float2*)(redf + ml * RED_STRIDE + 8 * j + 2 * gc) = v;
                }
            }
    }
    __syncthreads();
    if (grp == 0) {
#pragma unroll
        for (int i = 0; i < 2; i++)
#pragma unroll
            for (int rh = 0; rh < 2; rh++) {
                const int ml = wid_l * 32 + i * 16 + rh * 8 + gr;
#pragma unroll
                for (int j = 0; j < 8; j++) {
                    float2 v = *(float2*)(redf + ml * RED_STRIDE + 8 * j + 2 * gc);
                    acc[i][j][rh * 2]     += v.x;
                    acc[i][j][rh * 2 + 1] += v.y;
                }
            }

        // ---- epilogue: top-2 + smem flags + outputs ----
#pragma unroll
        for (int i = 0; i < 2; i++) {
#pragma unroll
            for (int rh = 0; rh < 2; rh++) {
                const int m = wid_l * 32 + i * 16 + rh * 8 + gr;
                Top3 t; t.v0 = -1e30f; t.v1 = -1e30f; t.v2 = -1e30f; t.i0 = 0; t.i1 = 0;
#pragma unroll
                for (int j = 0; j < 8; j++) {
#pragma unroll
                    for (int b = 0; b < 2; b++)
                        t3_insert(t, acc[i][j][rh * 2 + b], 8 * j + 2 * gc + b);
                }
                t3_merge_xor(t, 1);
                t3_merge_xor(t, 2);

                const size_t g = (size_t)(mbase + m);
                if (gc == 0) {
                    float e1  = expf(t.v1 - t.v0);
                    float inv = 1.0f / (1.0f + e1);
                    out_w[g * 2 + 0] = inv;
                    out_w[g * 2 + 1] = e1 * inv;
                    out_i[g * 2 + 0] = (float)t.i0;
                    out_i[g * 2 + 1] = (float)t.i1;
                    if ((t.v0 - t.v1 < DELTA) || (t.v1 - t.v2 < DELTA)) {
                        int slot = atomicAdd(&s_cnt, 1);
                        if (slot < FCAP) s_list[slot] = m;
                    }
                }
                float* mrow = out_mask + g * NEXP + gc * 16;
#pragma unroll
                for (int q = 0; q < 4; q++) {
                    int e0 = gc * 16 + q * 4;
                    float4 mv;
                    mv.x = (e0 + 0 == t.i0 || e0 + 0 == t.i1) ? 1.0f : 0.0f;
                    mv.y = (e0 + 1 == t.i0 || e0 + 1 == t.i1) ? 1.0f : 0.0f;
                    mv.z = (e0 + 2 == t.i0 || e0 + 2 == t.i1) ? 1.0f : 0.0f;
                    mv.w = (e0 + 3 == t.i0 || e0 + 3 == t.i1) ? 1.0f : 0.0f;
                    *(float4*)(mrow + q * 4) = mv;
                }
            }
        }
    }

    // ================= in-CTA exact repair of flagged tokens =================
    __syncthreads();
    int cnt = s_cnt;
    if (cnt > FCAP) cnt = FCAP;
    if (cnt > 0) {
        float* xs = (float*)smem;            // 8KB, stage area is dead now
        float* lg = (float*)(smem + 8192);   // 64 floats
        const int e    = tid >> 2;           // expert
        const int part = tid & 3;            // interleaved float4 k-part

        for (int it = 0; it < cnt; it++) {
            const int m = s_list[it];
            const size_t tok = (size_t)(mbase + m);
            __syncthreads();
            {
                const float4* xrow = (const float4*)(x + tok * DIMK);
                for (int q = tid; q < DIMK / 4; q += NT)
                    ((float4*)xs)[q] = xrow[q];
            }
            __syncthreads();

            const float4* wrow = (const float4*)(w + (size_t)e * DIMK);
            const float4* xp   = (const float4*)xs;
            float4 accv = make_float4(0, 0, 0, 0);
#pragma unroll 8
            for (int q = 0; q < 128; q++) {
                float4 xv = xp[4 * q + part];
                float4 wv = wrow[4 * q + part];
                accv.x = fmaf(xv.x, wv.x, accv.x);
                accv.y = fmaf(xv.y, wv.y, accv.y);
                accv.z = fmaf(xv.z, wv.z, accv.z);
                accv.w = fmaf(xv.w, wv.w, accv.w);
            }
            float s = (accv.x + accv.y) + (accv.z + accv.w);
            s += __shfl_xor_sync(0xFFFFFFFFu, s, 1);
            s += __shfl_xor_sync(0xFFFFFFFFu, s, 2);
            if (part == 0) lg[e] = s;
            __syncthreads();

            if (tid < 32) {
                Top3 t; t.v0 = -1e30f; t.v1 = -1e30f; t.v2 = -1e30f; t.i0 = 0; t.i1 = 0;
                t3_insert(t, lg[tid], tid);
                t3_insert(t, lg[tid + 32], tid + 32);
                t3_merge_xor(t, 1);
                t3_merge_xor(t, 2);
                t3_merge_xor(t, 4);
                t3_merge_xor(t, 8);
                t3_merge_xor(t, 16);

                int i0 = __shfl_sync(0xFFFFFFFFu, t.i0, 0);
                int i1 = __shfl_sync(0xFFFFFFFFu, t.i1, 0);
                if (tid == 0) {
                    float e1  = expf(t.v1 - t.v0);
                    float inv = 1.0f / (1.0f + e1);
                    out_w[tok * 2 + 0] = inv;
                    out_w[tok * 2 + 1] = e1 * inv;
                    out_i[tok * 2 + 0] = (float)i0;
                    out_i[tok * 2 + 1] = (float)i1;
                }
                out_mask[tok * NEXP + tid] =
                    (tid == i0 || tid == i1) ? 1.0f : 0.0f;
                out_mask[tok * NEXP + tid + 32] =
                    (tid + 32 == i0 || tid + 32 == i1) ? 1.0f : 0.0f;
            }
        }
    }
}

extern "C" void kernel_launch(void* const* d_in, const int* in_sizes, int n_in,
                              void* d_out, int out_size) {
    const float* x = (const float*)d_in[0];   // (N, 2048) fp32
    const float* w = (const float*)d_in[1];   // (64, 2048) fp32
    int n_tokens = in_sizes[0] / DIMK;        // 32768

    float* out      = (float*)d_out;
    float* out_mask = out;                                  // N*64
    float* out_w    = out + (size_t)n_tokens * NEXP;        // N*2
    float* out_i    = out_w + (size_t)n_tokens * 2;         // N*2

    static bool attr_done = false;
    if (!attr_done) {
        cudaFuncSetAttribute(router_mma, cudaFuncAttributeMaxDynamicSharedMemorySize, SMEMB);
        attr_done = true;
    }

    router_mma<<<n_tokens / BM, NT, SMEMB>>>(x, w, out_mask, out_w, out_i);
}